// round 14
// baseline (speedup 1.0000x reference)
#include <cuda_runtime.h>
#include <cstring>

#define NQ     18
#define NREPS  3
#define NBATCH 64
#define IDIM   32

__device__ __forceinline__ float2 cmul(float2 a, float2 b) {
    return make_float2(a.x * b.x - a.y * b.y, a.x * b.y + a.y * b.x);
}
__device__ __forceinline__ float2 cmulc(float2 a, float2 b) {   // a * conj(b)
    return make_float2(a.x * b.x + a.y * b.y, a.y * b.x - a.x * b.y);
}
// packed f32x2 add (sm_100a): one instruction for a complex add
__device__ __forceinline__ float2 cadd(float2 a, float2 b) {
    unsigned long long ua, ub, uo;
    memcpy(&ua, &a, 8); memcpy(&ub, &b, 8);
    asm("add.rn.f32x2 %0, %1, %2;" : "=l"(uo) : "l"(ua), "l"(ub));
    float2 o; memcpy(&o, &uo, 8);
    return o;
}
__device__ __forceinline__ float2 csub(float2 a, float2 b) {
    return make_float2(a.x - b.x, a.y - b.y);
}
__device__ __forceinline__ float2 shflx(float2 v, int m) {
    float2 r;
    r.x = __shfl_xor_sync(0xffffffffu, v.x, m);
    r.y = __shfl_xor_sync(0xffffffffu, v.y, m);
    return r;
}
// load 8 consecutive float2 (64B, 16B-aligned) as 4x LDS.128
__device__ __forceinline__ void ldrow8(const float2* p, float2* r) {
    const float4* q = (const float4*)p;
    float4 v0 = q[0], v1 = q[1], v2 = q[2], v3 = q[3];
    r[0] = make_float2(v0.x, v0.y); r[1] = make_float2(v0.z, v0.w);
    r[2] = make_float2(v1.x, v1.y); r[3] = make_float2(v1.z, v1.w);
    r[4] = make_float2(v2.x, v2.y); r[5] = make_float2(v2.z, v2.w);
    r[6] = make_float2(v3.x, v3.y); r[7] = make_float2(v3.z, v3.w);
}
// 4-accumulator complex dot: sum_m x[m]*y[m]
__device__ __forceinline__ float2 cdot8(const float2* x, const float2* y) {
    float2 a0 = cmul(x[0], y[0]);
    float2 a1 = cmul(x[1], y[1]);
    float2 a2 = cmul(x[2], y[2]);
    float2 a3 = cmul(x[3], y[3]);
    a0 = cadd(a0, cmul(x[4], y[4]));
    a1 = cadd(a1, cmul(x[5], y[5]));
    a2 = cadd(a2, cmul(x[6], y[6]));
    a3 = cadd(a3, cmul(x[7], y[7]));
    return cadd(cadd(a0, a1), cadd(a2, a3));
}
// 4-accumulator conj dot: sum_m x[m]*conj(y[m])
__device__ __forceinline__ float2 cdot8c(const float2* x, const float2* y) {
    float2 a0 = cmulc(x[0], y[0]);
    float2 a1 = cmulc(x[1], y[1]);
    float2 a2 = cmulc(x[2], y[2]);
    float2 a3 = cmulc(x[3], y[3]);
    a0 = cadd(a0, cmulc(x[4], y[4]));
    a1 = cadd(a1, cmulc(x[5], y[5]));
    a2 = cadd(a2, cmulc(x[6], y[6]));
    a3 = cadd(a3, cmulc(x[7], y[7]));
    return cadd(cadd(a0, a1), cadd(a2, a3));
}

#define SIDE_BAR(sd) asm volatile("bar.sync %0, %1;" :: "r"(1 + (sd)), "r"(64) : "memory")

// Matrix rows padded to 10 float2 (80B); (pr,q) blocks 82 f2. Layout (bytes):
//   [0,      23616)  M  [9][4] blocks of 82 f2, rows [8][10]   (right sweep)
//   [23616,  47232)  MH = M^dagger, same layout                (left sweep)
//   [47232,  70272)  G (build) -> histories rhoH/sigH/Dh/SH [9][8][10] f2 each
//                    (history also serves as the per-step env exchange buffer)
//   [70272,  93312)  GT (build) -> TL transpose buffers (2 sides x 400 f2)
#define SMEM_BYTES 93312

__global__ __launch_bounds__(512, 1) void qenc_kernel(
    const float* __restrict__ xin,   // (64, 32)
    const float* __restrict__ vp,    // (3, 18, 2)
    float* __restrict__ out)         // (64, 18)
{
    extern __shared__ __align__(16) char dyn[];
    float2* Mb    = (float2*)(dyn);
    float2* MHb   = (float2*)(dyn + 23616);
    float2* Gb    = (float2*)(dyn + 47232);
    float2* GTb   = (float2*)(dyn + 70272);
    float2* hist  = (float2*)(dyn + 47232);
    float2* tlb   = (float2*)(dyn + 70272);

    __shared__ float sc[NQ][5][2];
    __shared__ float zred[NQ][8];

#define MROW(pr,qq,r)  (Mb  + ((pr)*4+(qq))*82 + (r)*10)
#define MHROW(pr,qq,r) (MHb + ((pr)*4+(qq))*82 + (r)*10)
#define GROW(k,z,r)    (Gb  + ((k)*2+(z))*80 + (r)*10)
#define GTROW(k,z,r)   (GTb + ((k)*2+(z))*80 + (r)*10)
#define HROW(arr,s,r)  (hist + (arr)*720 + (s)*80 + (r)*10)
#define HEL(arr,s,r,c) hist[(arr)*720 + (s)*80 + (r)*10 + (c)]
#define TLROW(sd,ii,qq) (tlb + (sd)*400 + ((ii)*4+(qq))*10)

    const int b   = blockIdx.x;
    const int tid = threadIdx.x;

    // ---- setup: 5 sincos per site (RY(a)RY(b)=RY(a+b) collapses products) --
    if (tid < NQ * 5) {
        const int k = tid / 5;
        const int g = tid - k * 5;
        float th;
        if (g == 0)      th = vp[(0 * NQ + k) * 2 + 0];
        else if (g == 1) th = vp[(1 * NQ + k) * 2 + 0] + vp[(0 * NQ + k) * 2 + 1];
        else if (g == 2) th = vp[(2 * NQ + k) * 2 + 0] + vp[(1 * NQ + k) * 2 + 1];
        else if (g == 3) th = vp[(2 * NQ + k) * 2 + 1];
        else             th = xin[b * IDIM + k];
        float s, c;
        __sincosf(0.5f * th, &s, &c);
        sc[k][g][0] = c;
        sc[k][g][1] = s;
    }
    __syncthreads();

    // ---- build G[k][z][p][n] and its transpose ------------------------------
    #pragma unroll
    for (int ii = 0; ii < 5; ++ii) {
        const int idx = tid + ii * 512;
        if (idx < NQ * 128) {
            const int k = idx >> 7;
            const int z = (idx >> 6) & 1;
            const int p = (idx >> 3) & 7;
            const int n = idx & 7;
            const int n1 = n & 1, n2 = (n >> 1) & 1, n3 = (n >> 2) & 1;
            const int p1 = p & 1, p2 = (p >> 1) & 1, p3 = (p >> 2) & 1;
            const float r3  = (z == n3) ? sc[k][3][0] : (z == 0 ? -sc[k][3][1] : sc[k][3][1]);
            const int   i3  = n3 ^ p3;
            const float rc3 = (i3 == n2) ? sc[k][2][0] : (i3 == 0 ? -sc[k][2][1] : sc[k][2][1]);
            const int   i2  = n2 ^ p2;
            const float rc2 = (i2 == n1) ? sc[k][1][0] : (i2 == 0 ? -sc[k][1][1] : sc[k][1][1]);
            const float coef = r3 * rc3 * rc2;
            const float c1 = sc[k][0][0], s1 = sc[k][0][1];
            const float cx = sc[k][4][0], sx = sc[k][4][1];
            float2 w;
            if ((n1 ^ p1) == 0) w = make_float2(c1 * cx,  s1 * sx);
            else                w = make_float2(s1 * cx, -c1 * sx);
            const float2 val = make_float2(coef * w.x, coef * w.y);
            GROW(k, z, p)[n] = val;
            GTROW(k, z, n)[p] = val;
        }
    }
    __syncthreads();

    // ---- build M[pr][q] = G[2pr][z1]*G[2pr+1][z2], MH = M^dagger (1x2 tile) --
    #pragma unroll
    for (int ii = 0; ii < 3; ++ii) {
        const int idx = tid + ii * 512;
        if (idx < 9 * 4 * 8 * 4) {
            const int pr  = idx >> 7;
            const int rem = idx & 127;
            const int qx  = rem >> 5;
            const int p   = (rem >> 2) & 7;
            const int n0  = (rem & 3) * 2;
            const int z1 = qx >> 1, z2 = qx & 1;
            float2 ra[8], rb0[8], rb1[8];
            ldrow8(GROW(2 * pr, z1, p), ra);
            ldrow8(GTROW(2 * pr + 1, z2, n0), rb0);
            ldrow8(GTROW(2 * pr + 1, z2, n0 + 1), rb1);
            const float2 acc0 = cdot8(ra, rb0);
            const float2 acc1 = cdot8(ra, rb1);
            MROW(pr, qx, p)[n0]     = acc0;
            MROW(pr, qx, p)[n0 + 1] = acc1;
            MHROW(pr, qx, n0)[p]     = make_float2(acc0.x, -acc0.y);
            MHROW(pr, qx, n0 + 1)[p] = make_float2(acc1.x, -acc1.y);
        }
    }
    __syncthreads();   // G/GT dead; regions become histories / TL buffers

    // ---- boundary history slots (epilogue reads these; done by spare tids) --
    if (tid >= 128 && tid < 192) {
        const int j = tid - 128;
        HEL(0, 0, j >> 3, j & 7) = make_float2(j == 0 ? 1.f : 0.f, 0.f);  // rho^0
    } else if (tid >= 192 && tid < 256) {
        const int j = tid - 192;
        HEL(1, 0, j >> 3, j & 7) = make_float2(1.f, 0.f);                 // J
    }

    // ---- sweeps: 2 warps per side, 64-thread barriers, env rows in regs -----
    if (tid < 128) {
        const int side  = tid >> 6;         // 0 = left, 1 = right
        const int ihalf = (tid >> 5) & 1;   // which 4 i-rows this warp owns
        const int lane  = tid & 31;
        const int q     = lane >> 3;
        const int a     = lane & 7;
        const int z2    = q & 1;
        const int z1    = q >> 1;

        // boundary env row a in registers: left rho^0 = e0 e0^T, right sig = J
        float2 row[8];
        #pragma unroll
        for (int m = 0; m < 8; ++m)
            row[m] = (side == 0)
                   ? make_float2((a == 0 && m == 0) ? 1.f : 0.f, 0.f)
                   : make_float2(1.f, 0.f);

        #pragma unroll
        for (int s = 0; s < 9; ++s) {
            // stage1: tl[ii] for owned i rows
            float2 tl[4];
            #pragma unroll
            for (int ii = 0; ii < 4; ++ii) {
                const int i = ihalf * 4 + ii;
                float2 mi[8];
                if (side == 0) {
                    ldrow8(MHROW(s, q, i), mi);
                    const float2 acc = cdot8(mi, row);        // sum MH[i][m]*rho[a][m]
                    tl[ii] = make_float2(acc.x, -acc.y);      // conj
                } else {
                    ldrow8(MROW(8 - s, q, i), mi);
                    tl[ii] = cdot8c(mi, row);                 // sum M[i][m]*conj(sig[a][m])
                }
            }
            // transpose within warp via smem
            #pragma unroll
            for (int ii = 0; ii < 4; ++ii)
                TLROW(side, ihalf * 4 + ii, q)[a] = tl[ii];
            __syncwarp();

            // stage2 + reductions; mrow reused across the 4 i's
            float2 mrow[8];
            if (side == 0) ldrow8(MHROW(s, q, a), mrow);
            else           ldrow8(MROW(8 - s, q, a), mrow);

            #pragma unroll
            for (int ii = 0; ii < 4; ++ii) {
                const int i = ihalf * 4 + ii;
                float2 trow[8];
                ldrow8(TLROW(side, i, q), trow);
                const float2 t = (side == 0) ? cdot8(trow, mrow)
                                             : cdot8c(trow, mrow);
                const float2 u     = shflx(t, 8);
                const float2 sum2  = cadd(t, u);
                const float2 dif2  = z2 ? csub(u, t) : csub(t, u);
                const float2 s2o   = shflx(sum2, 16);
                const float2 sum4  = cadd(sum2, s2o);
                const float2 d2o   = shflx(dif2, 16);
                const float2 difz2 = cadd(dif2, d2o);
                const float2 difz1 = z1 ? csub(s2o, sum2) : csub(sum2, s2o);
                if (side == 0) {
                    if (q == 0)      { if (s < 8) HEL(0, s + 1, i, a) = sum4; }
                    else if (q == 1) HEL(2, s, i, a) = difz2;      // D[2s+1]
                } else {
                    if (q == 0)      { if (s < 8) HEL(1, s + 1, i, a) = sum4; }
                    else if (q == 1) HEL(3, s, i, a) = difz1;      // S[16-2s]
                }
            }
            SIDE_BAR(side);
            if (s < 8) ldrow8(HROW(side, s + 1, a), row);   // next env row a
        }
    }
    __syncthreads();   // join: epilogue reads all histories

    // ---- observables --------------------------------------------------------
    // even t=2e: Re(rhoH[e] . SH[8-e]);  odd t=2e+1: Re(Dh[e] . sigH[8-e])
    if (tid < NQ * 8) {
        const int w = tid >> 3;
        const int r = tid & 7;
        const int e = w >> 1;
        const float2* dmat = (w & 1) ? HROW(2, e, r)     : HROW(0, e, r);
        const float2* smat = (w & 1) ? HROW(1, 8 - e, r) : HROW(3, 8 - e, r);
        float2 d[8], sm[8];
        ldrow8(dmat, d);
        ldrow8(smat, sm);
        float acc = 0.f;
        #pragma unroll
        for (int j = 0; j < 8; ++j)
            acc += d[j].x * sm[j].x - d[j].y * sm[j].y;
        zred[w][r] = acc;
    }
    __syncthreads();
    if (tid < NQ) {
        float sum = 0.f;
        #pragma unroll
        for (int j = 0; j < 8; ++j) sum += zred[tid][j];
        out[b * NQ + tid] = sum;
    }
}

extern "C" void kernel_launch(void* const* d_in, const int* in_sizes, int n_in,
                              void* d_out, int out_size)
{
    const float* x  = (const float*)d_in[0];   // input_vec (64,32)
    const float* vp = (const float*)d_in[1];   // var_params (3,18,2)
    if (n_in >= 2 && in_sizes[0] == NREPS * NQ * 2) {
        x  = (const float*)d_in[1];
        vp = (const float*)d_in[0];
    }
    cudaFuncSetAttribute(qenc_kernel,
                         cudaFuncAttributeMaxDynamicSharedMemorySize, SMEM_BYTES);
    qenc_kernel<<<NBATCH, 512, SMEM_BYTES>>>(x, vp, (float*)d_out);
}

// round 15
// speedup vs baseline: 1.7299x; 1.7299x over previous
#include <cuda_runtime.h>
#include <cstring>

#define NQ     18
#define NREPS  3
#define NBATCH 64
#define IDIM   32

__device__ __forceinline__ float2 cmul(float2 a, float2 b) {
    return make_float2(a.x * b.x - a.y * b.y, a.x * b.y + a.y * b.x);
}
__device__ __forceinline__ float2 cmulc(float2 a, float2 b) {   // a * conj(b)
    return make_float2(a.x * b.x + a.y * b.y, a.y * b.x - a.x * b.y);
}
// packed f32x2 add (sm_100a): one instruction for a complex add
__device__ __forceinline__ float2 cadd(float2 a, float2 b) {
    unsigned long long ua, ub, uo;
    memcpy(&ua, &a, 8); memcpy(&ub, &b, 8);
    asm("add.rn.f32x2 %0, %1, %2;" : "=l"(uo) : "l"(ua), "l"(ub));
    float2 o; memcpy(&o, &uo, 8);
    return o;
}
__device__ __forceinline__ float2 csub(float2 a, float2 b) {
    return make_float2(a.x - b.x, a.y - b.y);
}
__device__ __forceinline__ float2 shflx(float2 v, int m) {
    float2 r;
    r.x = __shfl_xor_sync(0xffffffffu, v.x, m);
    r.y = __shfl_xor_sync(0xffffffffu, v.y, m);
    return r;
}
// RY rotation entry: R[i][j] = [[c,-s],[s,c]]
__device__ __forceinline__ float rsel(float c, float s, int i, int j) {
    return (i == j) ? c : (i ? s : -s);
}
// load 8 consecutive float2 (64B, 16B-aligned) as 4x LDS.128
__device__ __forceinline__ void ldrow8(const float2* p, float2* r) {
    const float4* q = (const float4*)p;
    float4 v0 = q[0], v1 = q[1], v2 = q[2], v3 = q[3];
    r[0] = make_float2(v0.x, v0.y); r[1] = make_float2(v0.z, v0.w);
    r[2] = make_float2(v1.x, v1.y); r[3] = make_float2(v1.z, v1.w);
    r[4] = make_float2(v2.x, v2.y); r[5] = make_float2(v2.z, v2.w);
    r[6] = make_float2(v3.x, v3.y); r[7] = make_float2(v3.z, v3.w);
}
// 4-accumulator complex dot: sum_m x[m]*y[m]
__device__ __forceinline__ float2 cdot8(const float2* x, const float2* y) {
    float2 a0 = cmul(x[0], y[0]);
    float2 a1 = cmul(x[1], y[1]);
    float2 a2 = cmul(x[2], y[2]);
    float2 a3 = cmul(x[3], y[3]);
    a0 = cadd(a0, cmul(x[4], y[4]));
    a1 = cadd(a1, cmul(x[5], y[5]));
    a2 = cadd(a2, cmul(x[6], y[6]));
    a3 = cadd(a3, cmul(x[7], y[7]));
    return cadd(cadd(a0, a1), cadd(a2, a3));
}
// 4-accumulator conj dot: sum_m x[m]*conj(y[m])
__device__ __forceinline__ float2 cdot8c(const float2* x, const float2* y) {
    float2 a0 = cmulc(x[0], y[0]);
    float2 a1 = cmulc(x[1], y[1]);
    float2 a2 = cmulc(x[2], y[2]);
    float2 a3 = cmulc(x[3], y[3]);
    a0 = cadd(a0, cmulc(x[4], y[4]));
    a1 = cadd(a1, cmulc(x[5], y[5]));
    a2 = cadd(a2, cmulc(x[6], y[6]));
    a3 = cadd(a3, cmulc(x[7], y[7]));
    return cadd(cadd(a0, a1), cadd(a2, a3));
}

#define HALF_BAR(h) asm volatile("bar.sync %0, %1;" :: "r"(1 + (h)), "r"(256) : "memory")

// Matrix rows padded to 10 float2 (80B); (pr,q) blocks 82 f2. Layout (bytes):
//   [0,      23616)  M  [9][4] blocks of 82 f2, rows [8][10]   (right sweep)
//   [23616,  47232)  MH = M^dagger, same layout                (left sweep)
//   [47232,  70272)  histories rhoH/sigH/Dh/SH [9][8][10] f2 each
//   [70272,  84096)  K (real, 288 rows x 12 floats) -> tmpL/tmpR in sweep
#define SMEM_BYTES 84096

__global__ __launch_bounds__(512, 1) void qenc_kernel(
    const float* __restrict__ xin,   // (64, 32)
    const float* __restrict__ vp,    // (3, 18, 2)
    float* __restrict__ out)         // (64, 18)
{
    extern __shared__ __align__(16) char dyn[];
    float2* Mb    = (float2*)(dyn);
    float2* MHb   = (float2*)(dyn + 23616);
    float2* hist  = (float2*)(dyn + 47232);
    float*  Kb    = (float*)(dyn + 70272);
    float2* tmpLb = (float2*)(dyn + 70272);
    float2* tmpRb = (float2*)(dyn + 70272 + 288 * 8);

    __shared__ float sc[NQ][5][2];
    __shared__ float zred[NQ][8];

#define MROW(pr,qq,r)  (Mb  + ((pr)*4+(qq))*82 + (r)*10)
#define MHROW(pr,qq,r) (MHb + ((pr)*4+(qq))*82 + (r)*10)
#define HROW(arr,s,r)  (hist + (arr)*720 + (s)*80 + (r)*10)
#define HEL(arr,s,r,c) hist[(arr)*720 + (s)*80 + (r)*10 + (c)]
#define TL(qq,ii)      (tmpLb + (ii)*36 + (qq)*8)
#define TR(qq,ii)      (tmpRb + (ii)*36 + (qq)*8)
#define KROW(rid)      (Kb + (rid) * 12)

    const int b   = blockIdx.x;
    const int tid = threadIdx.x;

    // ---- setup: 5 sincos per site (RY(a)RY(b)=RY(a+b) collapses products) --
    if (tid < NQ * 5) {
        const int k = tid / 5;
        const int g = tid - k * 5;
        float th;
        if (g == 0)      th = vp[(0 * NQ + k) * 2 + 0];
        else if (g == 1) th = vp[(1 * NQ + k) * 2 + 0] + vp[(0 * NQ + k) * 2 + 1];
        else if (g == 2) th = vp[(2 * NQ + k) * 2 + 0] + vp[(1 * NQ + k) * 2 + 1];
        else if (g == 3) th = vp[(2 * NQ + k) * 2 + 1];
        else             th = xin[b * IDIM + k];
        float s, c;
        __sincosf(0.5f * th, &s, &c);
        sc[k][g][0] = c;
        sc[k][g][1] = s;
    }
    __syncthreads();

    // ---- build K[pr][q][m1][p3p2][n] (REAL; batch-indep coefficient tensor)
    // K = sum_{m2,m3} C1[z1][p][m] * C2[z2][m][n]  with C = product of 3 RY
    // entries; w (complex, batch-dep) factored out entirely.
    if (tid < 288) {
        const int pr  = tid >> 5;
        const int rem = tid & 31;
        const int q   = rem >> 3;
        const int m1  = (rem >> 2) & 1;
        const int p3  = (rem >> 1) & 1;
        const int p2  = rem & 1;
        const int z1 = q >> 1, z2 = q & 1;
        const int k1 = 2 * pr, k2 = 2 * pr + 1;
        const float AaC = sc[k1][3][0], AaS = sc[k1][3][1];
        const float AbC = sc[k1][2][0], AbS = sc[k1][2][1];
        const float AcC = sc[k1][1][0], AcS = sc[k1][1][1];
        const float BaC = sc[k2][3][0], BaS = sc[k2][3][1];
        const float BbC = sc[k2][2][0], BbS = sc[k2][2][1];
        const float BcC = sc[k2][1][0], BcS = sc[k2][1][1];
        // t[m3][m2] = Ra[z1][m3] * Rb[m3^p3][m2] * Rc[m2^p2][m1]
        float t[2][2];
        #pragma unroll
        for (int m3 = 0; m3 < 2; ++m3) {
            const float am3 = rsel(AaC, AaS, z1, m3);
            #pragma unroll
            for (int m2 = 0; m2 < 2; ++m2)
                t[m3][m2] = am3 * rsel(AbC, AbS, m3 ^ p3, m2)
                                * rsel(AcC, AcS, m2 ^ p2, m1);
        }
        // in2[m3][n2][n1] = sum_m2 t[m3][m2] * RBc[n2^m2][n1]
        float in2[2][2][2];
        #pragma unroll
        for (int m3 = 0; m3 < 2; ++m3)
            #pragma unroll
            for (int n2 = 0; n2 < 2; ++n2)
                #pragma unroll
                for (int n1 = 0; n1 < 2; ++n1)
                    in2[m3][n2][n1] = t[m3][0] * rsel(BcC, BcS, n2, n1)
                                    + t[m3][1] * rsel(BcC, BcS, n2 ^ 1, n1);
        // out[n] = RBa[z2][n3] * sum_m3 in2[m3][n2][n1] * RBb[n3^m3][n2]
        float outr[8];
        #pragma unroll
        for (int n3 = 0; n3 < 2; ++n3) {
            const float ba = rsel(BaC, BaS, z2, n3);
            #pragma unroll
            for (int n2 = 0; n2 < 2; ++n2)
                #pragma unroll
                for (int n1 = 0; n1 < 2; ++n1) {
                    const float v = in2[0][n2][n1] * rsel(BbC, BbS, n3, n2)
                                  + in2[1][n2][n1] * rsel(BbC, BbS, n3 ^ 1, n2);
                    outr[4 * n3 + 2 * n2 + n1] = ba * v;
                }
        }
        float* kr = KROW(((pr * 4 + q) * 2 + m1) * 4 + (p3 * 2 + p2));
        *(float4*)(kr)     = make_float4(outr[0], outr[1], outr[2], outr[3]);
        *(float4*)(kr + 4) = make_float4(outr[4], outr[5], outr[6], outr[7]);
    }
    __syncthreads();

    // ---- M[pr][q][p][n] = sum_{m1} w1[m1^p1] w2[n1^m1] K[m1][p][n] ---------
    // w_k[0] = (c1*cx, s1*sx), w_k[1] = (s1*cx, -c1*sx)  (RX(x)|0> thru RY(A1))
    if (tid < 288) {
        const int pr  = tid >> 5;
        const int rem = tid & 31;
        const int q   = rem >> 3;
        const int p   = rem & 7;
        const int p1  = p & 1;
        const int k1 = 2 * pr, k2 = 2 * pr + 1;
        const float c1a = sc[k1][0][0], s1a = sc[k1][0][1];
        const float cxa = sc[k1][4][0], sxa = sc[k1][4][1];
        const float c1b = sc[k2][0][0], s1b = sc[k2][0][1];
        const float cxb = sc[k2][4][0], sxb = sc[k2][4][1];
        float2 w1[2], w2[2];
        w1[0] = make_float2(c1a * cxa,  s1a * sxa);
        w1[1] = make_float2(s1a * cxa, -c1a * sxa);
        w2[0] = make_float2(c1b * cxb,  s1b * sxb);
        w2[1] = make_float2(s1b * cxb, -c1b * sxb);
        // ca[n1] = w1[p1]*w2[n1]; cb[n1] = w1[p1^1]*w2[n1^1]
        const float2 ca0 = cmul(w1[p1], w2[0]);
        const float2 ca1 = cmul(w1[p1], w2[1]);
        const float2 cb0 = cmul(w1[p1 ^ 1], w2[1]);
        const float2 cb1 = cmul(w1[p1 ^ 1], w2[0]);
        const int base = (pr * 4 + q) * 8 + (p >> 1);
        const float* k0 = KROW(base);        // m1 = 0
        const float* k1r = KROW(base + 4);   // m1 = 1
        float4 a0 = *(const float4*)(k0),  a1 = *(const float4*)(k0 + 4);
        float4 b0 = *(const float4*)(k1r), b1 = *(const float4*)(k1r + 4);
        const float K0[8] = {a0.x, a0.y, a0.z, a0.w, a1.x, a1.y, a1.z, a1.w};
        const float K1[8] = {b0.x, b0.y, b0.z, b0.w, b1.x, b1.y, b1.z, b1.w};
        float2* mrow = MROW(pr, q, p);
        #pragma unroll
        for (int n = 0; n < 8; ++n) {
            const float2 cc = (n & 1) ? ca1 : ca0;
            const float2 cd = (n & 1) ? cb1 : cb0;
            const float2 v = make_float2(cc.x * K0[n] + cd.x * K1[n],
                                         cc.y * K0[n] + cd.y * K1[n]);
            mrow[n] = v;
            MHROW(pr, q, n)[p] = make_float2(v.x, -v.y);
        }
    }
    __syncthreads();   // K dead; its region becomes the sweep tmp buffers

    // ---- lane roles: warp = owned row i; lane = (q, a) ----------------------
    const int half = tid >> 8;          // 0 = left sweep, 1 = right sweep
    const int i    = (tid >> 5) & 7;    // warp-in-half = row
    const int lane = tid & 31;
    const int q    = lane >> 3;
    const int a    = lane & 7;
    const int z2   = q & 1;
    const int z1   = q >> 1;

    // ---- step s = 0 (boundary envs trivial; single stage) -------------------
    {
        float2 t;
        if (half == 0) {
            // rho^(0) = e0 e0^T: t_q[i][a] = M_q[0][i] * conj(M_q[0][a])
            t = cmulc(MHROW(0, q, a)[0], MHROW(0, q, i)[0]);
        } else {
            // sigma^(18) = J: t_q[i][a] = rowsum(M_q,i) * conj(rowsum(M_q,a))
            float2 mi[8], ma[8];
            ldrow8(MROW(8, q, i), mi);
            ldrow8(MROW(8, q, a), ma);
            float2 ri = make_float2(0.f, 0.f), rj = make_float2(0.f, 0.f);
            #pragma unroll
            for (int m = 0; m < 8; ++m) { ri = cadd(ri, mi[m]); rj = cadd(rj, ma[m]); }
            t = cmulc(ri, rj);
        }
        const float2 u    = shflx(t, 8);
        const float2 sum2 = cadd(t, u);
        const float2 dif2 = z2 ? csub(u, t) : csub(t, u);      // t(z2=0)-t(z2=1)
        const float2 s2o  = shflx(sum2, 16);
        const float2 sum4 = cadd(sum2, s2o);
        const float2 d2o  = shflx(dif2, 16);
        const float2 difz2 = cadd(dif2, d2o);
        const float2 difz1 = z1 ? csub(s2o, sum2) : csub(sum2, s2o);
        if (half == 0) {
            if (q == 0)      HEL(0, 1, i, a) = sum4;                            // rho^(2)
            else if (q == 1) HEL(2, 0, i, a) = difz2;                           // D[1]
            else if (q == 2) HEL(0, 0, i, a) = make_float2((i == 0 && a == 0) ? 1.f : 0.f, 0.f);
        } else {
            if (q == 0)      HEL(1, 1, i, a) = sum4;                            // sig^(16)
            else if (q == 1) HEL(3, 0, i, a) = difz1;                           // S[16]
            else if (q == 2) HEL(1, 0, i, a) = make_float2(1.f, 0.f);           // J
        }
    }
    HALF_BAR(half);

    // ---- steps s = 1..8 (fully unrolled; per-half named barriers) -----------
    #pragma unroll
    for (int s = 1; s < 9; ++s) {
        float2 t;
        if (half == 0) {
            // stage1: TL[q][i][a] = conj( sum_m MH_q[i][m] * rho[a][m] )
            float2 r[8], mh[8];
            ldrow8(HROW(0, s, a), r);
            ldrow8(MHROW(s, q, i), mh);
            const float2 acc = cdot8(mh, r);
            TL(q, i)[a] = make_float2(acc.x, -acc.y);
            __syncwarp();
            // stage2: t = sum_{a2} TL[q][i][a2] * MH_q[a][a2]
            float2 tr[8], mr[8];
            ldrow8(TL(q, i), tr);
            ldrow8(MHROW(s, q, a), mr);
            t = cdot8(tr, mr);
        } else {
            const int pr = 8 - s;
            // stage1: TR[q][i][a] = sum_m M_q[i][m] * conj(sig[a][m])
            float2 r[8], mr[8];
            ldrow8(HROW(1, s, a), r);
            ldrow8(MROW(pr, q, i), mr);
            TR(q, i)[a] = cdot8c(mr, r);
            __syncwarp();
            // stage2: t = sum_{a2} TR[q][i][a2] * conj(M_q[a][a2])
            float2 tr[8], ma[8];
            ldrow8(TR(q, i), tr);
            ldrow8(MROW(pr, q, a), ma);
            t = cdot8c(tr, ma);
        }
        const float2 u    = shflx(t, 8);
        const float2 sum2 = cadd(t, u);
        const float2 dif2 = z2 ? csub(u, t) : csub(t, u);
        const float2 s2o  = shflx(sum2, 16);
        const float2 sum4 = cadd(sum2, s2o);
        const float2 d2o  = shflx(dif2, 16);
        const float2 difz2 = cadd(dif2, d2o);
        const float2 difz1 = z1 ? csub(s2o, sum2) : csub(sum2, s2o);
        if (half == 0) {
            if (q == 0)      { if (s < 8) HEL(0, s + 1, i, a) = sum4; }
            else if (q == 1) HEL(2, s, i, a) = difz2;                  // D[2s+1]
        } else {
            if (q == 0)      { if (s < 8) HEL(1, s + 1, i, a) = sum4; }
            else if (q == 1) HEL(3, s, i, a) = difz1;                  // S[16-2s]
        }
        if (s < 8) HALF_BAR(half);   // last step is ordered by the join below
    }
    __syncthreads();   // join halves: epilogue reads both sides' histories

    // ---- observables --------------------------------------------------------
    // even t=2e: Re(rhoH[e] . SH[8-e]);  odd t=2e+1: Re(Dh[e] . sigH[8-e])
    if (tid < NQ * 8) {
        const int w = tid >> 3;
        const int r = tid & 7;
        const int e = w >> 1;
        const float2* dmat = (w & 1) ? HROW(2, e, r)     : HROW(0, e, r);
        const float2* smat = (w & 1) ? HROW(1, 8 - e, r) : HROW(3, 8 - e, r);
        float2 d[8], sm[8];
        ldrow8(dmat, d);
        ldrow8(smat, sm);
        float acc = 0.f;
        #pragma unroll
        for (int j = 0; j < 8; ++j)
            acc += d[j].x * sm[j].x - d[j].y * sm[j].y;
        zred[w][r] = acc;
    }
    __syncthreads();
    if (tid < NQ) {
        float sum = 0.f;
        #pragma unroll
        for (int j = 0; j < 8; ++j) sum += zred[tid][j];
        out[b * NQ + tid] = sum;
    }
}

extern "C" void kernel_launch(void* const* d_in, const int* in_sizes, int n_in,
                              void* d_out, int out_size)
{
    const float* x  = (const float*)d_in[0];   // input_vec (64,32)
    const float* vp = (const float*)d_in[1];   // var_params (3,18,2)
    if (n_in >= 2 && in_sizes[0] == NREPS * NQ * 2) {
        x  = (const float*)d_in[1];
        vp = (const float*)d_in[0];
    }
    cudaFuncSetAttribute(qenc_kernel,
                         cudaFuncAttributeMaxDynamicSharedMemorySize, SMEM_BYTES);
    qenc_kernel<<<NBATCH, 512, SMEM_BYTES>>>(x, vp, (float*)d_out);
}